// round 5
// baseline (speedup 1.0000x reference)
#include <cuda_runtime.h>
#include <cuda_bf16.h>
#include <cstdint>

// Problem constants
#define BB    4
#define CC    19
#define HWN   (512 * 1024)          // 524288 pixels per batch
#define NPIX  (BB * HWN)            // 2097152
#define NPIX4 (NPIX / 4)            // 524288
#define HW4   (HWN / 4)             // 131072 float4 per channel-plane
#define TOPK  1468006u              // int(0.7 * 2097152)
#define NBINS 4096
#define GRID  592                   // 148 SMs * 4 blocks  (co-resident, see launch_bounds)
#define TPB   256
#define NTHR  (GRID * TPB)          // 151552

// Scratch (static device arrays, zero-initialized at load; self-cleaned by
// block 0 at the end of every run so graph replays start clean)
__device__ float4       g_loss4[NPIX4];          // 8 MB pixel losses (L2-resident for P2)
__device__ unsigned int g_hist1[NBINS];          // coarse counts (bits >> 20)
__device__ unsigned int g_hist2[NBINS];          // fine counts ((bits>>8)&0xFFF) in b*
__device__ double       g_sum_gt;                // sum of values in coarse bins > b*
__device__ unsigned int g_barA;                  // grid barrier A counter
__device__ unsigned int g_barB;                  // grid barrier B counter (termination style)

// ---------------------------------------------------------------------------
// Single persistent kernel: P1 loss+coarse hist | barrier | P2 select+fine |
// barrier | P3 finalize (block 0) + self-clean.
// 592 blocks * 256 thr, 4 blocks/SM guaranteed by __launch_bounds__(256,4)
// (regs<=64, smem ~16.6KB) -> all blocks co-resident -> spin barriers safe.
// ---------------------------------------------------------------------------
__global__ void __launch_bounds__(TPB, 4)
fused_kernel(const float4* __restrict__ logits,
             const float4* __restrict__ smooth,
             const float*  __restrict__ w2,
             float* __restrict__ out) {
    __shared__ float    s_w[32];
    __shared__ unsigned s_h[NBINS];
    __shared__ unsigned s_wsum[8];
    __shared__ int      s_bin;      // bstar (P2) then fstar (P3)
    __shared__ unsigned s_need1;    // need from coarse crossing
    __shared__ unsigned s_need2;    // need from fine crossing
    __shared__ double   s_red[8];

    int t = threadIdx.x;
    int lane = t & 31, wid = t >> 5;

    // ======================= P1: loss + coarse histogram =======================
    if (t < CC) s_w[t] = w2[t];
    for (int i = t; i < NBINS; i += TPB) s_h[i] = 0u;
    __syncthreads();

    for (int tid = blockIdx.x * TPB + t; tid < NPIX4; tid += NTHR) {
        int p   = tid << 2;                    // pixel base index
        int b   = p >> 19;                     // batch  (p / HWN)
        int hw  = p & (HWN - 1);
        int base4 = b * (CC * HW4) + (hw >> 2);

        const float4* Lp = logits + base4;
        const float4* Sp = smooth + base4;

        float eX = 0.f, eY = 0.f, eZ = 0.f, eW = 0.f;        // sum exp
        float swX = 0.f, swY = 0.f, swZ = 0.f, swW = 0.f;    // sum s*w
        float slX = 0.f, slY = 0.f, slZ = 0.f, slW = 0.f;    // sum s*w*l

        #pragma unroll
        for (int c = 0; c < CC; c++) {
            float4 l = __ldcs(&Lp[c * HW4]);
            float4 s = __ldcs(&Sp[c * HW4]);
            float wc = s_w[c];
            eX += __expf(l.x); eY += __expf(l.y); eZ += __expf(l.z); eW += __expf(l.w);
            float a = s.x * wc, b2 = s.y * wc, c2 = s.z * wc, d2 = s.w * wc;
            swX += a;        swY += b2;       swZ += c2;       swW += d2;
            slX += a * l.x;  slY += b2 * l.y; slZ += c2 * l.z; slW += d2 * l.w;
        }

        float4 loss;
        loss.x = swX * __logf(eX) - slX;
        loss.y = swY * __logf(eY) - slY;
        loss.z = swZ * __logf(eZ) - slZ;
        loss.w = swW * __logf(eW) - slW;
        g_loss4[tid] = loss;

        atomicAdd(&s_h[__float_as_uint(loss.x) >> 20], 1u);
        atomicAdd(&s_h[__float_as_uint(loss.y) >> 20], 1u);
        atomicAdd(&s_h[__float_as_uint(loss.z) >> 20], 1u);
        atomicAdd(&s_h[__float_as_uint(loss.w) >> 20], 1u);
    }
    __syncthreads();
    for (int i = t; i < NBINS; i += TPB) {
        unsigned c = s_h[i];
        if (c) atomicAdd(&g_hist1[i], c);
    }

    // ======================= Barrier A (all-resident spin) =====================
    __syncthreads();
    if (t == 0) {
        __threadfence();
        atomicAdd(&g_barA, 1u);
        while (*(volatile unsigned*)&g_barA < GRID) __nanosleep(64);
        __threadfence();
    }
    __syncthreads();

    // ======================= P2: bstar scan + fine pass ========================
    // zero s_h for reuse as fine histogram
    for (int i = t; i < NBINS; i += TPB) s_h[i] = 0u;

    // per-block coarse scan (16 bins/thread, identical in all blocks)
    {
        unsigned c[16];
        unsigned run = 0;
        #pragma unroll
        for (int j = 0; j < 16; j++) {
            run += __ldg(&g_hist1[4095 - (16 * t + j)]);
            c[j] = run;
        }
        unsigned x = run;
        #pragma unroll
        for (int o = 1; o < 32; o <<= 1) {
            unsigned y = __shfl_up_sync(0xffffffffu, x, o);
            if (lane >= o) x += y;
        }
        if (lane == 31) s_wsum[wid] = x;
        __syncthreads();
        unsigned base = 0;
        #pragma unroll
        for (int w = 0; w < 8; w++) base += (w < wid) ? s_wsum[w] : 0u;
        unsigned ex = base + (x - run);
        #pragma unroll
        for (int j = 0; j < 16; j++) {
            unsigned cum  = ex + c[j];
            unsigned prev = j ? (ex + c[j - 1]) : ex;
            if (cum >= TOPK && prev < TOPK) { s_bin = 4095 - (16 * t + j); s_need1 = TOPK - prev; }
        }
    }
    __syncthreads();                 // covers s_h zero + scan results
    unsigned bstar = (unsigned)s_bin;
    unsigned need1 = s_need1;

    // streaming pass over L2-resident losses
    float acc0 = 0.f, acc1 = 0.f, acc2 = 0.f, acc3 = 0.f;
    for (int i = blockIdx.x * TPB + t; i < NPIX4; i += NTHR) {
        float4 v = g_loss4[i];
        unsigned bx = __float_as_uint(v.x);
        unsigned by = __float_as_uint(v.y);
        unsigned bz = __float_as_uint(v.z);
        unsigned bw = __float_as_uint(v.w);
        if ((bx >> 20) > bstar) acc0 += v.x;
        else if ((bx >> 20) == bstar) atomicAdd(&s_h[(bx >> 8) & 0xFFFu], 1u);
        if ((by >> 20) > bstar) acc1 += v.y;
        else if ((by >> 20) == bstar) atomicAdd(&s_h[(by >> 8) & 0xFFFu], 1u);
        if ((bz >> 20) > bstar) acc2 += v.z;
        else if ((bz >> 20) == bstar) atomicAdd(&s_h[(bz >> 8) & 0xFFFu], 1u);
        if ((bw >> 20) > bstar) acc3 += v.w;
        else if ((bw >> 20) == bstar) atomicAdd(&s_h[(bw >> 8) & 0xFFFu], 1u);
    }

    // block-reduce sum_gt (promote to double only here)
    double gt = (double)acc0 + (double)acc1 + (double)acc2 + (double)acc3;
    #pragma unroll
    for (int o = 16; o; o >>= 1) gt += __shfl_down_sync(0xffffffffu, gt, o);
    if (lane == 0) s_red[wid] = gt;
    __syncthreads();
    if (t == 0) {
        double s = 0.0;
        #pragma unroll
        for (int i = 0; i < 8; i++) s += s_red[i];
        atomicAdd(&g_sum_gt, s);
    }
    // merge fine counts (nonzero bins only)
    for (int i = t; i < NBINS; i += TPB) {
        unsigned c = s_h[i];
        if (c) atomicAdd(&g_hist2[i], c);
    }

    // ============ Barrier B (termination style: non-zero blocks exit) ==========
    __syncthreads();
    if (t == 0) { __threadfence(); atomicAdd(&g_barB, 1u); }
    if (blockIdx.x != 0) return;
    if (t == 0) {
        while (*(volatile unsigned*)&g_barB < GRID) __nanosleep(64);
        __threadfence();
    }
    __syncthreads();

    // ======================= P3: finalize (block 0 only) ======================
    int fstar; unsigned need2;
    {
        unsigned c[16];
        unsigned run = 0;
        #pragma unroll
        for (int j = 0; j < 16; j++) {
            run += g_hist2[4095 - (16 * t + j)];
            c[j] = run;
        }
        unsigned x = run;
        #pragma unroll
        for (int o = 1; o < 32; o <<= 1) {
            unsigned y = __shfl_up_sync(0xffffffffu, x, o);
            if (lane >= o) x += y;
        }
        if (lane == 31) s_wsum[wid] = x;
        __syncthreads();
        unsigned base = 0;
        #pragma unroll
        for (int w = 0; w < 8; w++) base += (w < wid) ? s_wsum[w] : 0u;
        unsigned ex = base + (x - run);
        #pragma unroll
        for (int j = 0; j < 16; j++) {
            unsigned cum  = ex + c[j];
            unsigned prev = j ? (ex + c[j - 1]) : ex;
            if (cum >= need1 && prev < need1) { s_bin = 4095 - (16 * t + j); s_need2 = need1 - prev; }
        }
    }
    __syncthreads();
    fstar = s_bin;
    need2 = s_need2;

    // sum of cnt * midpoint for fine bins strictly above fstar
    double acc = 0.0;
    #pragma unroll
    for (int j = 0; j < 16; j++) {
        int fb = 16 * t + j;
        if (fb > fstar) {
            unsigned cnt = g_hist2[fb];
            if (cnt) {
                float mid = __uint_as_float((bstar << 20) | ((unsigned)fb << 8) | 0x80u);
                acc += (double)cnt * (double)mid;
            }
        }
    }
    #pragma unroll
    for (int o = 16; o; o >>= 1) acc += __shfl_down_sync(0xffffffffu, acc, o);
    if (lane == 0) s_red[wid] = acc;
    __syncthreads();
    if (t == 0) {
        double fine_above = 0.0;
        #pragma unroll
        for (int i = 0; i < 8; i++) fine_above += s_red[i];
        float midt = __uint_as_float((bstar << 20) | ((unsigned)fstar << 8) | 0x80u);
        double total = g_sum_gt + fine_above + (double)need2 * (double)midt;
        out[0] = (float)(total / (double)TOPK);
    }
    __syncthreads();   // hist2 reads complete before zeroing

    // self-clean scratch for the next graph replay
    for (int i = t; i < NBINS; i += TPB) { g_hist1[i] = 0u; g_hist2[i] = 0u; }
    if (t == 0) {
        g_sum_gt = 0.0;
        g_barA = 0u;     // safe: every block passed barrier A before arriving at B
        g_barB = 0u;     // safe: only block 0 ever reads g_barB
    }
}

// ---------------------------------------------------------------------------
extern "C" void kernel_launch(void* const* d_in, const int* in_sizes, int n_in,
                              void* d_out, int out_size) {
    const float4* logits = (const float4*)d_in[0];
    // d_in[1] = labels (int64) — unused by the reference computation
    const float4* smooth = (const float4*)d_in[2];
    const float*  w2     = (const float*)d_in[3];
    float* out = (float*)d_out;

    fused_kernel<<<GRID, TPB>>>(logits, smooth, w2, out);
}